// round 9
// baseline (speedup 1.0000x reference)
#include <cuda_runtime.h>

#define BB 4
#define CC 64
#define TN 64
#define NN 4096
#define GRID 256
#define XS 68            // xs row stride (floats): 16B-aligned rows, conflict-free GEMM reads

typedef unsigned long long ull;

// scratch (allocation-free rule: __device__ globals, zero-initialized)
__device__ float g_Spart[BB * 64];        // per-tile partial sums of a
__device__ float g_upart[64 * BB * CC];   // [tile][b*CC+c]
__device__ float g_vpart[64 * BB * CC];
__device__ float g_W0t[CC * CC];          // [c][o]
__device__ float g_W1t[CC * CC];          // [c][o]
__device__ float g_scale[CC];
__device__ float g_shift[CC];
__device__ unsigned g_bar;                // monotonic barrier counter

// ---- f32x2 packed helpers ---------------------------------------------------
__device__ __forceinline__ ull pack2(float lo, float hi) {
    ull r; asm("mov.b64 %0, {%1, %2};" : "=l"(r) : "f"(lo), "f"(hi)); return r;
}
__device__ __forceinline__ void unpack2(ull v, float& lo, float& hi) {
    asm("mov.b64 {%0, %1}, %2;" : "=f"(lo), "=f"(hi) : "l"(v));
}
__device__ __forceinline__ ull fma2(ull a, ull b, ull c) {
    ull d; asm("fma.rn.f32x2 %0, %1, %2, %3;" : "=l"(d) : "l"(a), "l"(b), "l"(c)); return d;
}
__device__ __forceinline__ ull mul2(ull a, ull b) {
    ull d; asm("mul.rn.f32x2 %0, %1, %2;" : "=l"(d) : "l"(a), "l"(b)); return d;
}

__device__ __forceinline__ float relutanh(float x) {
    if (x <= 0.f) return 0.f;
    float e = __expf(-2.f * x);
    return (1.f - e) * __frcp_rn(1.f + e);
}

// device-wide barrier: monotonic counter (release writer-side, acquire reader-side)
__device__ __forceinline__ void grid_barrier(int tid) {
    __threadfence();
    __syncthreads();
    if (tid == 0) {
        unsigned old = atomicAdd(&g_bar, 1u);
        unsigned target = (old & ~(unsigned)(GRID - 1)) + GRID;
        unsigned vcur;
        do { vcur = *(volatile unsigned*)&g_bar; } while ((int)(vcur - target) < 0);
        __threadfence();
    }
    __syncthreads();
}

// -----------------------------------------------------------------------------
// Single fused kernel. grid=256, 256 threads. blk -> (b = blk>>6, tile = blk&63).
// x read from global exactly ONCE (phase A stage); a/d live in smem only.
// -----------------------------------------------------------------------------
__global__ void __launch_bounds__(256, 2) k_fused(
        const float* __restrict__ x,
        const float* __restrict__ w,
        const float* __restrict__ conv_w,
        const float* __restrict__ conv_b,
        const float* __restrict__ gamma,
        const float* __restrict__ beta,
        const float* __restrict__ mean,
        const float* __restrict__ var,
        float* __restrict__ out) {
    extern __shared__ float sm[];
    float* xs  = sm;                  // [64][XS] x tile        ~17KB
    float* w0s = sm + CC * XS;        // [c][o]                 16KB
    float* w1s = w0s + CC * CC;       //                        16KB
    __shared__ float a_s[64], d_s[64], ad_s[64];
    __shared__ float p_s[CC], q_s[CC], u_s[CC], v_s[CC];
    __shared__ float upart[4 * 64], vpart[4 * 64];
    __shared__ float redS[2];
    __shared__ float S_sh;

    const int tid = threadIdx.x;
    const int blk = blockIdx.x;
    const int b = blk >> 6;
    const int tile = blk & 63;
    const int n0 = tile * TN;

    // ================= Phase A =================
    // stage x tile [64][64] -> xs (stride XS)
    {
        const float* xb = x + (size_t)(b * CC) * NN + n0;
        #pragma unroll
        for (int k = 0; k < 4; k++) {
            int i = tid + k * 256;          // 1024 float4 = 64 rows x 16
            int cc2 = i >> 4, j = i & 15;
            float4 v = ((const float4*)(xb + cc2 * NN))[j];
            *(float4*)(xs + cc2 * XS + j * 4) = v;
        }
    }
    // tile-local a + partial S
    if (tid < 64) {
        float a = relutanh(w[b * NN + n0 + tid]);
        a_s[tid] = a;
        float s = a;
        #pragma unroll
        for (int off = 16; off; off >>= 1) s += __shfl_down_sync(0xffffffffu, s, off);
        if ((tid & 31) == 0) redS[tid >> 5] = s;
    }
    // b==0 blocks: transpose weight row c=tile; blk 0: BN fold
    if (b == 0) {
        if (tid < 64) {
            g_W0t[tile * CC + tid] = conv_w[tid * 128 + tile];
            g_W1t[tile * CC + tid] = conv_w[tid * 128 + CC + tile];
        }
        if (tile == 0 && tid >= 128 && tid < 192) {
            int o = tid - 128;
            float sc = gamma[o] * rsqrtf(var[o] + 1e-5f);
            g_scale[o] = sc;
            g_shift[o] = fmaf(conv_b[o] - mean[o], sc, beta[o]);
        }
    }
    __syncthreads();
    if (tid == 0) g_Spart[b * 64 + tile] = redS[0] + redS[1];

    // ================= Barrier 1 =================
    grid_barrier(tid);

    // ================= Phase B =================
    // stage weights (coalesced, L2-hot)
    {
        float4* w0s4 = (float4*)w0s;
        float4* w1s4 = (float4*)w1s;
        const float4* gw0 = (const float4*)g_W0t;
        const float4* gw1 = (const float4*)g_W1t;
        #pragma unroll
        for (int k = 0; k < 4; k++) {
            int i = tid + k * 256;          // 1024 float4 each
            w0s4[i] = gw0[i];
            w1s4[i] = gw1[i];
        }
    }
    // S = sum of 64 partials for batch b
    if (tid < 64) {
        float s = g_Spart[b * 64 + tid];
        #pragma unroll
        for (int off = 16; off; off >>= 1) s += __shfl_down_sync(0xffffffffu, s, off);
        if ((tid & 31) == 0) redS[tid >> 5] = s;
    }
    __syncthreads();
    if (tid == 0) S_sh = redS[0] + redS[1];
    __syncthreads();
    if (tid < 64) {
        float dd = rsqrtf(fmaf(a_s[tid], S_sh, 1.f));
        d_s[tid] = dd;
        ad_s[tid] = a_s[tid] * dd;
    }
    __syncthreads();
    // partial u/v over this tile: thread (c = tid&63, h = tid>>6) sums 16 j
    {
        const int cpart = tid & 63;
        const int h = tid >> 6;
        const float* xr = xs + cpart * XS + h * 16;
        const float* ap = a_s + h * 16;
        const float* dp = ad_s + h * 16;
        float su = 0.f, sv = 0.f;
        #pragma unroll
        for (int i = 0; i < 16; i += 2) {
            float2 xv = *(const float2*)(xr + i);
            su = fmaf(xv.x, ap[i], su);
            su = fmaf(xv.y, ap[i + 1], su);
            sv = fmaf(xv.x, dp[i], sv);
            sv = fmaf(xv.y, dp[i + 1], sv);
        }
        upart[h * 64 + cpart] = su;
        vpart[h * 64 + cpart] = sv;
    }
    __syncthreads();
    if (tid < 64) {
        g_upart[tile * (BB * CC) + b * CC + tid] =
            upart[tid] + upart[64 + tid] + upart[128 + tid] + upart[192 + tid];
    } else if (tid < 128) {
        int c = tid - 64;
        g_vpart[tile * (BB * CC) + b * CC + c] =
            vpart[c] + vpart[64 + c] + vpart[128 + c] + vpart[192 + c];
    }

    // ================= Barrier 2 =================
    grid_barrier(tid);

    // ================= Phase C =================
    // aggregate u/v (64 coalesced L2 loads each, fixed order -> deterministic)
    if (tid < 64) {
        float s = 0.f;
        #pragma unroll 8
        for (int t = 0; t < 64; t++) s += g_upart[t * (BB * CC) + b * CC + tid];
        u_s[tid] = s;
    } else if (tid < 128) {
        int c = tid - 64;
        float s = 0.f;
        #pragma unroll 8
        for (int t = 0; t < 64; t++) s += g_vpart[t * (BB * CC) + b * CC + c];
        v_s[c] = s;
    }
    __syncthreads();

    // p[o] = sum_c W0t[c][o] u[c] ; q[o] = sum_c W1t[c][o] v[c]
    if (tid < 128) {
        const int o = tid & 63;
        const bool isq = tid >= 64;
        const float* W = isq ? w1s : w0s;
        const float* uv = isq ? v_s : u_s;
        float s = 0.f;
        #pragma unroll 8
        for (int cc2 = 0; cc2 < CC; cc2++) s = fmaf(W[cc2 * CC + o], uv[cc2], s);
        (isq ? q_s : p_s)[o] = s;
    }
    __syncthreads();

    const int warp = tid >> 5, lane = tid & 31;
    const int ow = warp << 3;           // 8 o per warp (4 o-pairs)
    const int nl = 2 * lane;            // 2 n per lane (tile-local)
    const int ng = n0 + nl;

    const float2 a2 = *(const float2*)(a_s + nl);
    const float2 d2 = *(const float2*)(d_s + nl);
    const ull ddp0 = pack2(d2.x * d2.x, d2.x * d2.x);
    const ull ddp1 = pack2(d2.y * d2.y, d2.y * d2.y);

    ull acc[4][2];                      // [o-pair][n]
    #pragma unroll
    for (int i = 0; i < 4; i++) { acc[i][0] = 0ull; acc[i][1] = 0ull; }

    const float* xp  = xs  + nl;
    const float* w0p = w0s + ow;
    const float* w1p = w1s + ow;

    #pragma unroll 8
    for (int k = 0; k < CC; k++) {
        float2 xv = *(const float2*)(xp + k * XS);
        ull xd0 = pack2(xv.x, xv.x);
        ull xd1 = pack2(xv.y, xv.y);
        ull xq0 = mul2(xd0, ddp0);
        ull xq1 = mul2(xd1, ddp1);
        ulonglong2 wa0 = *(const ulonglong2*)(w0p + k * CC);
        ulonglong2 wb0 = *(const ulonglong2*)(w0p + k * CC + 4);
        ulonglong2 wa1 = *(const ulonglong2*)(w1p + k * CC);
        ulonglong2 wb1 = *(const ulonglong2*)(w1p + k * CC + 4);
        acc[0][0] = fma2(wa0.x, xd0, acc[0][0]);
        acc[0][1] = fma2(wa0.x, xd1, acc[0][1]);
        acc[1][0] = fma2(wa0.y, xd0, acc[1][0]);
        acc[1][1] = fma2(wa0.y, xd1, acc[1][1]);
        acc[2][0] = fma2(wb0.x, xd0, acc[2][0]);
        acc[2][1] = fma2(wb0.x, xd1, acc[2][1]);
        acc[3][0] = fma2(wb0.y, xd0, acc[3][0]);
        acc[3][1] = fma2(wb0.y, xd1, acc[3][1]);
        acc[0][0] = fma2(wa1.x, xq0, acc[0][0]);
        acc[0][1] = fma2(wa1.x, xq1, acc[0][1]);
        acc[1][0] = fma2(wa1.y, xq0, acc[1][0]);
        acc[1][1] = fma2(wa1.y, xq1, acc[1][1]);
        acc[2][0] = fma2(wb1.x, xq0, acc[2][0]);
        acc[2][1] = fma2(wb1.x, xq1, acc[2][1]);
        acc[3][0] = fma2(wb1.y, xq0, acc[3][0]);
        acc[3][1] = fma2(wb1.y, xq1, acc[3][1]);
    }

    // epilogue: y = acc + p*a_n + q*(d*a)_n ; BN ; ReLU
    const ull ap0  = pack2(a2.x, a2.x);
    const ull ap1  = pack2(a2.y, a2.y);
    const ull dap0 = pack2(d2.x * a2.x, d2.x * a2.x);
    const ull dap1 = pack2(d2.y * a2.y, d2.y * a2.y);

    float* ob = out + (size_t)(b * CC) * NN + ng;
    #pragma unroll
    for (int j = 0; j < 4; j++) {
        const int o0 = ow + 2 * j;
        ull pp = *(const ull*)(p_s + o0);
        ull qq = *(const ull*)(q_s + o0);
        ull sc = *(const ull*)(g_scale + o0);
        ull sh = *(const ull*)(g_shift + o0);
        ull y0 = fma2(pp, ap0, acc[j][0]);
        y0 = fma2(qq, dap0, y0);
        y0 = fma2(y0, sc, sh);
        ull y1 = fma2(pp, ap1, acc[j][1]);
        y1 = fma2(qq, dap1, y1);
        y1 = fma2(y1, sc, sh);
        float f00, f10, f01, f11;
        unpack2(y0, f00, f10);
        unpack2(y1, f01, f11);
        f00 = fmaxf(f00, 0.f); f01 = fmaxf(f01, 0.f);
        f10 = fmaxf(f10, 0.f); f11 = fmaxf(f11, 0.f);
        *(float2*)(ob + (size_t)o0 * NN)       = make_float2(f00, f01);
        *(float2*)(ob + (size_t)(o0 + 1) * NN) = make_float2(f10, f11);
    }
}

// -----------------------------------------------------------------------------
extern "C" void kernel_launch(void* const* d_in, const int* in_sizes, int n_in,
                              void* d_out, int out_size) {
    const float* x      = (const float*)d_in[0];
    const float* w      = (const float*)d_in[1];
    const float* conv_w = (const float*)d_in[2];
    const float* conv_b = (const float*)d_in[3];
    const float* gamma  = (const float*)d_in[4];
    const float* beta   = (const float*)d_in[5];
    const float* mean   = (const float*)d_in[6];
    const float* var    = (const float*)d_in[7];
    float* out = (float*)d_out;

    const int smem = (CC * XS + 2 * CC * CC) * sizeof(float);  // ~49 KB
    cudaFuncSetAttribute(k_fused, cudaFuncAttributeMaxDynamicSharedMemorySize, smem);

    k_fused<<<GRID, 256, smem>>>(x, w, conv_w, conv_b, gamma, beta, mean, var, out);
}

// round 10
// speedup vs baseline: 1.1945x; 1.1945x over previous
#include <cuda_runtime.h>

#define BB 4
#define CC 64
#define TN 64
#define NN 4096
#define GRID 256

typedef unsigned long long ull;

// scratch (allocation-free rule: __device__ globals, zero-initialized)
__device__ float g_a[BB * NN];
__device__ float g_d[BB * NN];
__device__ float g_u[BB * CC];
__device__ float g_v[BB * CC];
__device__ float g_W0t[CC * CC];     // [c][o]
__device__ float g_W1t[CC * CC];     // [c][o]
__device__ float g_scale[CC];
__device__ float g_shift[CC];
__device__ unsigned g_bar;           // monotonic barrier counter

// ---- f32x2 packed helpers ---------------------------------------------------
__device__ __forceinline__ ull pack2(float lo, float hi) {
    ull r; asm("mov.b64 %0, {%1, %2};" : "=l"(r) : "f"(lo), "f"(hi)); return r;
}
__device__ __forceinline__ void unpack2(ull v, float& lo, float& hi) {
    asm("mov.b64 {%0, %1}, %2;" : "=f"(lo), "=f"(hi) : "l"(v));
}
__device__ __forceinline__ ull fma2(ull a, ull b, ull c) {
    ull d; asm("fma.rn.f32x2 %0, %1, %2, %3;" : "=l"(d) : "l"(a), "l"(b), "l"(c)); return d;
}

__device__ __forceinline__ float relutanh(float x) {
    if (x <= 0.f) return 0.f;
    float e = __expf(-2.f * x);
    return (1.f - e) * __frcp_rn(1.f + e);
}

// device-wide barrier: monotonic counter
__device__ __forceinline__ void grid_barrier(int tid) {
    __threadfence();
    __syncthreads();
    if (tid == 0) {
        unsigned old = atomicAdd(&g_bar, 1u);
        unsigned target = (old & ~(unsigned)(GRID - 1)) + GRID;
        unsigned vcur;
        do { vcur = *(volatile unsigned*)&g_bar; } while ((int)(vcur - target) < 0);
        __threadfence();
    }
    __syncthreads();
}

// -----------------------------------------------------------------------------
// Single fused kernel (R6 structure). grid=256, 256 threads, 48KB dyn smem.
// Phase 1: block (b = blk>>6, c = blk&63): a,d in regs + u,v reduction;
//          c==0 writes g_a/g_d; b==0 transposes conv_w row c; (0,0) folds BN.
// Barrier, then Phase 2: split-accumulator f32x2 GEMM with prefetch-by-1.
// -----------------------------------------------------------------------------
__global__ void __launch_bounds__(256, 2) k_fused(
        const float* __restrict__ x,
        const float* __restrict__ w,
        const float* __restrict__ conv_w,
        const float* __restrict__ conv_b,
        const float* __restrict__ gamma,
        const float* __restrict__ beta,
        const float* __restrict__ mean,
        const float* __restrict__ var,
        float* __restrict__ out) {
    extern __shared__ float sm[];
    float* xs  = sm;                  // [64][64] plain x      16KB
    float* w0s = sm + CC * TN;        // [c][o]                16KB
    float* w1s = w0s + CC * CC;       //                       16KB
    __shared__ float p_s[CC], q_s[CC], u_s[CC], v_s[CC];
    __shared__ float red[8], red2[8];
    __shared__ float S_sh;

    const int tid = threadIdx.x;
    const int blk = blockIdx.x;
    const int b = blk >> 6;
    const int c = blk & 63;
    const int n0 = c * TN;            // phase-2 tile == c

    // ================= Phase 1 =================
    {
        const float4* w4 = (const float4*)(w + b * NN);
        float avr[16], dvr[16];
        float s = 0.f;
        #pragma unroll
        for (int k = 0; k < 4; k++) {
            float4 wv = w4[tid + k * 256];
            avr[k*4+0] = relutanh(wv.x);
            avr[k*4+1] = relutanh(wv.y);
            avr[k*4+2] = relutanh(wv.z);
            avr[k*4+3] = relutanh(wv.w);
            s += avr[k*4+0] + avr[k*4+1] + avr[k*4+2] + avr[k*4+3];
        }
        #pragma unroll
        for (int off = 16; off; off >>= 1) s += __shfl_down_sync(0xffffffffu, s, off);
        if ((tid & 31) == 0) red[tid >> 5] = s;
        __syncthreads();
        if (tid == 0) {
            float t = 0.f;
            #pragma unroll
            for (int i = 0; i < 8; i++) t += red[i];
            S_sh = t;
        }
        __syncthreads();
        const float S = S_sh;
        #pragma unroll
        for (int i = 0; i < 16; i++) dvr[i] = rsqrtf(fmaf(avr[i], S, 1.f));

        if (c == 0) {
            #pragma unroll
            for (int k = 0; k < 4; k++) {
                ((float4*)(g_a + b * NN))[tid + k * 256] =
                    make_float4(avr[k*4+0], avr[k*4+1], avr[k*4+2], avr[k*4+3]);
                ((float4*)(g_d + b * NN))[tid + k * 256] =
                    make_float4(dvr[k*4+0], dvr[k*4+1], dvr[k*4+2], dvr[k*4+3]);
            }
        }
        if (b == 0) {
            if (tid < CC) {
                g_W0t[c * CC + tid] = conv_w[tid * 128 + c];
                g_W1t[c * CC + tid] = conv_w[tid * 128 + CC + c];
            }
            if (c == 0 && tid >= 64 && tid < 128) {
                int o = tid - 64;
                float sc = gamma[o] * rsqrtf(var[o] + 1e-5f);
                g_scale[o] = sc;
                g_shift[o] = fmaf(conv_b[o] - mean[o], sc, beta[o]);
            }
        }

        // u = sum x*a ; v = sum x*a*d for channel (b,c)
        const float4* x4 = (const float4*)(x + (size_t)(b * CC + c) * NN);
        float su = 0.f, sv = 0.f;
        #pragma unroll
        for (int k = 0; k < 4; k++) {
            float4 xv = x4[tid + k * 256];
            float t0 = xv.x * avr[k*4+0], t1 = xv.y * avr[k*4+1];
            float t2 = xv.z * avr[k*4+2], t3 = xv.w * avr[k*4+3];
            su += t0 + t1 + t2 + t3;
            sv += t0 * dvr[k*4+0] + t1 * dvr[k*4+1] + t2 * dvr[k*4+2] + t3 * dvr[k*4+3];
        }
        #pragma unroll
        for (int off = 16; off; off >>= 1) {
            su += __shfl_down_sync(0xffffffffu, su, off);
            sv += __shfl_down_sync(0xffffffffu, sv, off);
        }
        if ((tid & 31) == 0) { red[tid >> 5] = su; red2[tid >> 5] = sv; }
        __syncthreads();
        if (tid == 0) {
            float tu = 0.f, tv = 0.f;
            #pragma unroll
            for (int i = 0; i < 8; i++) { tu += red[i]; tv += red2[i]; }
            g_u[b * CC + c] = tu;
            g_v[b * CC + c] = tv;
        }
    }

    // ================= device-wide barrier =================
    grid_barrier(tid);

    // ================= Phase 2 =================
    // stage: plain x tile [64][64], weights, u/v
    {
        const float* xb = x + (size_t)(b * CC) * NN + n0;
        float4* xs4 = (float4*)xs;
        #pragma unroll
        for (int k = 0; k < 4; k++) {
            int i = tid + k * 256;          // 1024 float4 = 64 rows x 16
            int cc2 = i >> 4, j = i & 15;
            xs4[i] = ((const float4*)(xb + cc2 * NN))[j];
        }
        float4* w0s4 = (float4*)w0s;
        float4* w1s4 = (float4*)w1s;
        const float4* gw0 = (const float4*)g_W0t;
        const float4* gw1 = (const float4*)g_W1t;
        #pragma unroll
        for (int k = 0; k < 4; k++) {
            int i = tid + k * 256;          // 1024 float4 each
            w0s4[i] = gw0[i];
            w1s4[i] = gw1[i];
        }
        if (tid < CC) {
            u_s[tid] = g_u[b * CC + tid];
            v_s[tid] = g_v[b * CC + tid];
        }
    }
    __syncthreads();

    // p[o] = sum_c W0t[c][o] u[c] ; q[o] = sum_c W1t[c][o] v[c]
    if (tid < 128) {
        const int o = tid & 63;
        const bool isq = tid >= 64;
        const float* W = isq ? w1s : w0s;
        const float* uv = isq ? v_s : u_s;
        float s = 0.f;
        #pragma unroll 8
        for (int cc2 = 0; cc2 < CC; cc2++) s = fmaf(W[cc2 * CC + o], uv[cc2], s);
        (isq ? q_s : p_s)[o] = s;
    }
    __syncthreads();

    const int warp = tid >> 5, lane = tid & 31;
    const int ow = warp << 3;           // 8 o per warp (4 o-pairs)
    const int ng = n0 + 2 * lane;       // 2 n per lane

    const float2 a2 = *(const float2*)(g_a + b * NN + ng);
    const float2 d2 = *(const float2*)(g_d + b * NN + ng);

    // split accumulator banks: acc0 = W0-x, acc1 = W1-x (d^2 applied in epilogue)
    ull acc0[4][2], acc1[4][2];
    #pragma unroll
    for (int i = 0; i < 4; i++) {
        acc0[i][0] = acc0[i][1] = 0ull;
        acc1[i][0] = acc1[i][1] = 0ull;
    }

    const float* xp  = xs  + 2 * lane;
    const float* w0p = w0s + ow;
    const float* w1p = w1s + ow;

    // prefetch-by-1 software pipeline
    float2 xv = *(const float2*)(xp);
    #pragma unroll 8
    for (int k = 0; k < CC; k++) {
        ull xd0 = pack2(xv.x, xv.x);
        ull xd1 = pack2(xv.y, xv.y);
        if (k + 1 < CC) xv = *(const float2*)(xp + (k + 1) * TN);
        ulonglong2 wa0 = *(const ulonglong2*)(w0p + k * CC);
        ulonglong2 wb0 = *(const ulonglong2*)(w0p + k * CC + 4);
        ulonglong2 wa1 = *(const ulonglong2*)(w1p + k * CC);
        ulonglong2 wb1 = *(const ulonglong2*)(w1p + k * CC + 4);
        acc0[0][0] = fma2(wa0.x, xd0, acc0[0][0]);
        acc0[0][1] = fma2(wa0.x, xd1, acc0[0][1]);
        acc0[1][0] = fma2(wa0.y, xd0, acc0[1][0]);
        acc0[1][1] = fma2(wa0.y, xd1, acc0[1][1]);
        acc0[2][0] = fma2(wb0.x, xd0, acc0[2][0]);
        acc0[2][1] = fma2(wb0.x, xd1, acc0[2][1]);
        acc0[3][0] = fma2(wb0.y, xd0, acc0[3][0]);
        acc0[3][1] = fma2(wb0.y, xd1, acc0[3][1]);
        acc1[0][0] = fma2(wa1.x, xd0, acc1[0][0]);
        acc1[0][1] = fma2(wa1.x, xd1, acc1[0][1]);
        acc1[1][0] = fma2(wa1.y, xd0, acc1[1][0]);
        acc1[1][1] = fma2(wa1.y, xd1, acc1[1][1]);
        acc1[2][0] = fma2(wb1.x, xd0, acc1[2][0]);
        acc1[2][1] = fma2(wb1.x, xd1, acc1[2][1]);
        acc1[3][0] = fma2(wb1.y, xd0, acc1[3][0]);
        acc1[3][1] = fma2(wb1.y, xd1, acc1[3][1]);
    }

    // epilogue: y = acc0 + d^2*acc1 + p*a_n + q*(d*a)_n ; BN ; ReLU
    const ull ddp0 = pack2(d2.x * d2.x, d2.x * d2.x);
    const ull ddp1 = pack2(d2.y * d2.y, d2.y * d2.y);
    const ull ap0  = pack2(a2.x, a2.x);
    const ull ap1  = pack2(a2.y, a2.y);
    const ull dap0 = pack2(d2.x * a2.x, d2.x * a2.x);
    const ull dap1 = pack2(d2.y * a2.y, d2.y * a2.y);

    float* ob = out + (size_t)(b * CC) * NN + ng;
    #pragma unroll
    for (int j = 0; j < 4; j++) {
        const int o0 = ow + 2 * j;
        ull pp = *(const ull*)(p_s + o0);
        ull qq = *(const ull*)(q_s + o0);
        ull sc = *(const ull*)(g_scale + o0);
        ull sh = *(const ull*)(g_shift + o0);
        ull y0 = fma2(acc1[j][0], ddp0, acc0[j][0]);
        y0 = fma2(pp, ap0, y0);
        y0 = fma2(qq, dap0, y0);
        y0 = fma2(y0, sc, sh);
        ull y1 = fma2(acc1[j][1], ddp1, acc0[j][1]);
        y1 = fma2(pp, ap1, y1);
        y1 = fma2(qq, dap1, y1);
        y1 = fma2(y1, sc, sh);
        float f00, f10, f01, f11;
        unpack2(y0, f00, f10);
        unpack2(y1, f01, f11);
        f00 = fmaxf(f00, 0.f); f01 = fmaxf(f01, 0.f);
        f10 = fmaxf(f10, 0.f); f11 = fmaxf(f11, 0.f);
        *(float2*)(ob + (size_t)o0 * NN)       = make_float2(f00, f01);
        *(float2*)(ob + (size_t)(o0 + 1) * NN) = make_float2(f10, f11);
    }
}

// -----------------------------------------------------------------------------
extern "C" void kernel_launch(void* const* d_in, const int* in_sizes, int n_in,
                              void* d_out, int out_size) {
    const float* x      = (const float*)d_in[0];
    const float* w      = (const float*)d_in[1];
    const float* conv_w = (const float*)d_in[2];
    const float* conv_b = (const float*)d_in[3];
    const float* gamma  = (const float*)d_in[4];
    const float* beta   = (const float*)d_in[5];
    const float* mean   = (const float*)d_in[6];
    const float* var    = (const float*)d_in[7];
    float* out = (float*)d_out;

    const int smem = (CC * TN + 2 * CC * CC) * sizeof(float);  // 48 KB
    cudaFuncSetAttribute(k_fused, cudaFuncAttributeMaxDynamicSharedMemorySize, smem);

    k_fused<<<GRID, 256, smem>>>(x, w, conv_w, conv_b, gamma, beta, mean, var, out);
}